// round 2
// baseline (speedup 1.0000x reference)
#include <cuda_runtime.h>
#include <cstdint>

// Problem constants
constexpr int B = 64;
constexpr int T = 1024;
constexpr int V = 512;
constexpr int L = 128;
constexpr int THREADS = 288;   // 9 warps; tid 0..256 each own one CTC state
constexpr int D = 6;           // per-thread LDG prefetch pipeline depth

#define NEG2   (-1.44269504e30f)          // -1e30 in log2 domain
#define LOG2E  1.4426950408889634f
#define LN2    0.6931471805599453f

__device__ float g_loss[B];
__device__ int   g_ctr = 0;

__device__ __forceinline__ float ex2f(float x) {
    float y; asm("ex2.approx.f32 %0, %1;" : "=f"(y) : "f"(x)); return y;
}
__device__ __forceinline__ float lg2f(float x) {
    float y; asm("lg2.approx.f32 %0, %1;" : "=f"(y) : "f"(x)); return y;
}

__global__ __launch_bounds__(THREADS, 1)
void ctc_fused_kernel(const float* __restrict__ outputs,
                      const int*   __restrict__ labels,
                      const int*   __restrict__ output_lengths,
                      const int*   __restrict__ label_lengths,
                      float* __restrict__ out) {
    // boundary exchange: bnd[buf][wid][0..1]; slot [*][0] = NEG source for warp 0,
    // slot [*][10] = write dump for lanes < 30.
    __shared__ __align__(8) float bnd[2][11][2];
    __shared__ float fin[2];

    const int b    = blockIdx.x;
    const int tid  = threadIdx.x;
    const int lane = tid & 31;
    const int wid  = tid >> 5;

    const int olen = output_lengths[b];
    const int llen = label_lengths[b];
    const int tcap = olen - 1;
    const int s0g  = 2 * llen - 1;
    const int s1g  = 2 * llen;
    const bool is0 = (tid == s0g);
    const bool is1 = (tid == s1g);

    // Static per-state info: column in the vocab row, and the skip flag.
    int  col  = 0;
    bool skip = false;
    if ((tid & 1) && tid < 257) {
        const int li = (tid - 1) >> 1;
        col = labels[b * L + li];
        if (li > 0) skip = (col != labels[b * L + li - 1]);
    }

    if (tid < 2) { bnd[0][0][tid] = NEG2; bnd[1][0][tid] = NEG2; }

    const float* gbase = outputs + (size_t)b * T * V + col;

    // Prefetch pipeline: ebuf[k] holds raw logit for row (t + k)
    float ebuf[D];
    #pragma unroll
    for (int k = 0; k < D; ++k)
        ebuf[k] = __ldcs(gbase + (size_t)k * V);

    __syncthreads();   // bnd NEG slots visible

    // ---- peeled t = 0 ----
    float e2 = ebuf[0] * LOG2E;
    #pragma unroll
    for (int k = 0; k < D - 1; ++k) ebuf[k] = ebuf[k + 1];
    {
        int tl = D; tl = (tl < T) ? tl : (T - 1);
        ebuf[D - 1] = __ldcs(gbase + (size_t)tl * V);
    }
    float v = (tid <= 1) ? e2 : NEG2;
    float cap0 = ((0 == tcap) && is0) ? v : NEG2;
    float cap1 = ((0 == tcap) && is1) ? v : NEG2;
    {
        float* bp = (lane >= 30) ? &bnd[1][wid + 1][lane - 30] : &bnd[1][10][0];
        *bp = v;
    }
    __syncthreads();

    // ---- main recursion, branch-free body ----
    for (int t = 1; t < T; ++t) {
        const int cb = t & 1;       // buffer holding step t-1 boundary values
        const int wb = cb ^ 1;

        // emit for row t (loaded D steps ago), refill pipeline
        const float et = ebuf[0] * LOG2E;
        #pragma unroll
        for (int k = 0; k < D - 1; ++k) ebuf[k] = ebuf[k + 1];
        int tl = t + D; tl = (tl < T) ? tl : (T - 1);
        ebuf[D - 1] = __ldcs(gbase + (size_t)tl * V);

        // neighbor alphas: own register + shuffles; warp boundary via SMEM
        const float b2 = bnd[cb][wid][0];   // alpha_prev[32*wid - 2]
        const float b1 = bnd[cb][wid][1];   // alpha_prev[32*wid - 1]
        float p1 = __shfl_up_sync(0xffffffffu, v, 1);
        float p2 = __shfl_up_sync(0xffffffffu, v, 2);
        p1 = (lane == 0) ? b1 : p1;
        p2 = (lane == 0) ? b2 : ((lane == 1) ? b1 : p2);
        const float p2f = skip ? p2 : NEG2;

        const float m   = fmaxf(v, fmaxf(p1, p2f));
        const float sum = ex2f(v - m) + ex2f(p1 - m) + ex2f(p2f - m);
        v = m + lg2f(sum) + et;

        // register-resident final-alpha capture (no branch)
        const bool pc = (t == tcap);
        cap0 = (pc && is0) ? v : cap0;
        cap1 = (pc && is1) ? v : cap1;

        // publish warp-top boundary values for step t
        float* bp = (lane >= 30) ? &bnd[wb][wid + 1][lane - 30] : &bnd[wb][10][0];
        *bp = v;
        __syncthreads();
    }

    // ---- per-batch finish ----
    if (is0) fin[0] = cap0;
    if (is1) fin[1] = cap1;
    __syncthreads();

    if (tid == 0) {
        const float a0 = fin[0];
        const float a1 = fin[1];
        const float m  = fmaxf(a0, a1);
        const float ll = (m + lg2f(ex2f(a0 - m) + ex2f(a1 - m))) * LN2;
        g_loss[b] = -ll / (float)llen;
        __threadfence();
        const int old = atomicAdd(&g_ctr, 1);
        if (old == B - 1) {
            __threadfence();
            float s = 0.0f;
            #pragma unroll 8
            for (int i = 0; i < B; ++i) s += g_loss[i];
            *out = s * (1.0f / (float)B);
            g_ctr = 0;   // reset for next graph replay
        }
    }
}

extern "C" void kernel_launch(void* const* d_in, const int* in_sizes, int n_in,
                              void* d_out, int out_size) {
    const float* outputs        = (const float*)d_in[0];
    const int*   labels         = (const int*)d_in[1];
    const int*   output_lengths = (const int*)d_in[2];
    const int*   label_lengths  = (const int*)d_in[3];
    float* out = (float*)d_out;

    ctc_fused_kernel<<<B, THREADS>>>(outputs, labels, output_lengths,
                                     label_lengths, out);
}

// round 3
// speedup vs baseline: 1.5998x; 1.5998x over previous
#include <cuda_runtime.h>
#include <cstdint>

constexpr int B = 64;
constexpr int T = 1024;
constexpr int V = 512;
constexpr int L = 128;
constexpr int NSTAGE = 6;        // cp.async row pipeline depth
constexpr int THREADS = 128;     // 4 warps; thread i owns states i and i+128 (+256 on tid 0)

#define NEG2   (-1.44269504e30f)     // -1e30 in log2 domain
#define LOG2E  1.4426950408889634f
#define LN2    0.6931471805599453f

__device__ float g_loss[B];
__device__ int   g_ctr = 0;

__device__ __forceinline__ float ex2f(float x) {
    float y; asm("ex2.approx.f32 %0, %1;" : "=f"(y) : "f"(x)); return y;
}
__device__ __forceinline__ float lg2f(float x) {
    float y; asm("lg2.approx.f32 %0, %1;" : "=f"(y) : "f"(x)); return y;
}
__device__ __forceinline__ float lse3(float a, float b, float c) {
    const float m = fmaxf(a, fmaxf(b, c));
    return m + lg2f(ex2f(a - m) + ex2f(b - m) + ex2f(c - m));
}
__device__ __forceinline__ float lse2(float a, float b) {
    const float m = fmaxf(a, b);
    const float d = fminf(a, b) - m;
    return m + lg2f(1.0f + ex2f(d));
}

__device__ __forceinline__ void cp_async16(uint32_t saddr, const void* gptr) {
    asm volatile("cp.async.cg.shared.global [%0], [%1], 16;\n" ::"r"(saddr), "l"(gptr));
}
__device__ __forceinline__ void cp_commit() {
    asm volatile("cp.async.commit_group;\n");
}
template <int N>
__device__ __forceinline__ void cp_wait() {
    asm volatile("cp.async.wait_group %0;\n" ::"n"(N));
}

__global__ __launch_bounds__(THREADS, 1)
void ctc_fused_kernel(const float* __restrict__ outputs,
                      const int*   __restrict__ labels,
                      const int*   __restrict__ output_lengths,
                      const int*   __restrict__ label_lengths,
                      float* __restrict__ out) {
    __shared__ __align__(16) float rowbuf[NSTAGE][V];    // 12 KB
    // bnd[buf][row][4]: rows 0..3 = per-warp publish {vlo30,vlo31,vhi30,vhi31},
    // row 4 = constant NEG pair for warp 0's low chain, row 5 = dump.
    __shared__ __align__(8) float bnd[2][6][4];
    __shared__ float fin[2];

    const int b    = blockIdx.x;
    const int tid  = threadIdx.x;
    const int lane = tid & 31;
    const int w    = tid >> 5;

    const int olen = output_lengths[b];
    const int llen = label_lengths[b];
    const int tcap = olen - 1;
    const int s0g  = 2 * llen - 1;
    const int s1g  = 2 * llen;

    // ---- static per-state data ----
    // low state s = tid, high state s = tid + 128, thread 0 also owns 256.
    const int*  lb_ptr = labels + b * L;
    int  col_lo = 0, col_hi = 0;
    bool skip_lo = false, skip_hi = false;
    if (tid & 1) {
        const int li = (tid - 1) >> 1;           // 0..63
        col_lo = lb_ptr[li];
        if (li > 0) skip_lo = (col_lo != lb_ptr[li - 1]);
        const int lih = li + 64;                 // 64..127
        col_hi = lb_ptr[lih];
        skip_hi = (col_hi != lb_ptr[lih - 1]);
    }

    const bool lo0 = (tid == s0g),        lo1 = (tid == s1g);
    const bool hi0 = (tid + 128 == s0g),  hi1 = (tid + 128 == s1g);
    const bool x1  = (tid == 0) && (s1g == 256);   // s0g is odd, never 256

    // boundary source indices (constant per thread)
    const int lw   = (w == 0) ? 4 : (w - 1);   // low-chain source row
    const int hw   = (w == 0) ? 3 : (w - 1);   // high-chain source row
    const int hoff = (w == 0) ? 0 : 2;         // warp0 high reads warp3's LOW pair
    // publish target (pointer-select, no branch)
    const int prow = (lane >= 30) ? w : 5;
    const int pidx = (lane >= 30) ? (lane - 30) : 0;

    if (tid < 8) bnd[tid >> 2][4][tid & 3] = NEG2;

    // ---- cp.async prologue: rows 0..NSTAGE-2 ----
    const float* gb = outputs + (size_t)b * T * V;
    const int le = tid * 4;                     // 16B per thread covers the 2KB row
    #pragma unroll
    for (int k = 0; k < NSTAGE - 1; ++k) {
        cp_async16((uint32_t)__cvta_generic_to_shared(&rowbuf[k][le]),
                   gb + (size_t)k * V + le);
        cp_commit();
    }

    cp_wait<NSTAGE - 2>();       // row 0 landed
    __syncthreads();             // + bnd NEG rows visible

    // ---- peeled t = 0 ----
    float vlo, vhi, v256;
    float cap0 = NEG2, cap1 = NEG2;
    {
        const float* row = rowbuf[0];
        const float e_lo = row[col_lo] * LOG2E;
        vlo  = (tid <= 1) ? e_lo : NEG2;
        vhi  = NEG2;
        v256 = NEG2;
        const bool pc = (tcap == 0);
        cap0 = (pc && lo0) ? vlo : cap0;
        cap1 = (pc && lo1) ? vlo : cap1;
        bnd[1][prow][pidx]     = vlo;
        bnd[1][prow][2 + pidx] = vhi;
        // prefetch row NSTAGE-1
        cp_async16((uint32_t)__cvta_generic_to_shared(&rowbuf[NSTAGE - 1][le]),
                   gb + (size_t)(NSTAGE - 1) * V + le);
        cp_commit();
    }

    // ---- main recursion ----
    int rs = 1;                                   // stage holding row t
    int ws = 0;                                   // stage to receive row t+NSTAGE-1
    for (int t = 1; t < T; ++t) {
        cp_wait<NSTAGE - 2>();                    // row t landed
        __syncthreads();                          // + bnd publish of step t-1

        const int   rb  = t & 1;
        const int   wb  = rb ^ 1;
        const float* row = rowbuf[rs];

        // emit gathers (SMEM)
        const float e_lo = row[col_lo] * LOG2E;
        const float e_hi = row[col_hi] * LOG2E;

        // boundary pairs (b2, b1)
        const float2 lbv = *(const float2*)&bnd[rb][lw][0];
        const float2 hbv = *(const float2*)&bnd[rb][hw][hoff];
        const float  a255 = bnd[rb][3][3];        // alpha_prev[255] for state 256

        // neighbor alphas
        float plo1 = __shfl_up_sync(0xffffffffu, vlo, 1);
        float plo2 = __shfl_up_sync(0xffffffffu, vlo, 2);
        float phi1 = __shfl_up_sync(0xffffffffu, vhi, 1);
        float phi2 = __shfl_up_sync(0xffffffffu, vhi, 2);
        plo1 = (lane == 0) ? lbv.y : plo1;
        plo2 = (lane == 0) ? lbv.x : ((lane == 1) ? lbv.y : plo2);
        phi1 = (lane == 0) ? hbv.y : phi1;
        phi2 = (lane == 0) ? hbv.x : ((lane == 1) ? hbv.y : phi2);

        const float p2lo = skip_lo ? plo2 : NEG2;
        const float p2hi = skip_hi ? phi2 : NEG2;

        const float nlo = lse3(vlo, plo1, p2lo) + e_lo;
        const float nhi = lse3(vhi, phi1, p2hi) + e_hi;
        const float n256 = lse2(v256, a255) + e_lo;   // valid on tid 0 (col_lo==0)
        vlo = nlo; vhi = nhi; v256 = n256;

        // branch-free captures
        const bool pc = (t == tcap);
        cap0 = (pc && lo0) ? vlo : cap0;
        cap0 = (pc && hi0) ? vhi : cap0;
        cap1 = (pc && lo1) ? vlo : cap1;
        cap1 = (pc && hi1) ? vhi : cap1;
        cap1 = (pc && x1)  ? v256 : cap1;

        // publish boundaries for step t
        bnd[wb][prow][pidx]     = vlo;
        bnd[wb][prow][2 + pidx] = vhi;

        // prefetch row t + NSTAGE - 1 (clamped; keeps group count uniform)
        int tp = t + NSTAGE - 1; tp = (tp < T) ? tp : (T - 1);
        cp_async16((uint32_t)__cvta_generic_to_shared(&rowbuf[ws][le]),
                   gb + (size_t)tp * V + le);
        cp_commit();

        rs = (rs + 1 == NSTAGE) ? 0 : rs + 1;
        ws = (ws + 1 == NSTAGE) ? 0 : ws + 1;
    }

    // ---- per-batch finish ----
    if (lo0 || hi0) fin[0] = cap0;
    if (lo1 || hi1 || x1) fin[1] = cap1;
    __syncthreads();

    if (tid == 0) {
        const float a0 = fin[0];
        const float a1 = fin[1];
        const float ll = lse2(a0, a1) * LN2;
        g_loss[b] = -ll / (float)llen;
        __threadfence();
        const int old = atomicAdd(&g_ctr, 1);
        if (old == B - 1) {
            __threadfence();
            float s = 0.0f;
            #pragma unroll 8
            for (int i = 0; i < B; ++i) s += g_loss[i];
            *out = s * (1.0f / (float)B);
            g_ctr = 0;   // reset for next graph replay
        }
    }
}

extern "C" void kernel_launch(void* const* d_in, const int* in_sizes, int n_in,
                              void* d_out, int out_size) {
    const float* outputs        = (const float*)d_in[0];
    const int*   labels         = (const int*)d_in[1];
    const int*   output_lengths = (const int*)d_in[2];
    const int*   label_lengths  = (const int*)d_in[3];
    float* out = (float*)d_out;

    ctc_fused_kernel<<<B, THREADS>>>(outputs, labels, output_lengths,
                                     label_lengths, out);
}